// round 15
// baseline (speedup 1.0000x reference)
#include <cuda_runtime.h>
#include <cuda_pipeline.h>
#include <cuda_fp16.h>
#include <mma.h>
#include <cstdint>
#include <cstddef>

using namespace nvcuda;

#define L_  6
#define B_  8
#define Q_  2048
#define C_  256
#define P_  128
#define FF_ 1024
#define R_  (B_*Q_)   // 16384 rows

static const size_t INTERM_OFF = 0;
static const size_t REFS_OFF   = (size_t)L_*R_*C_;                 // 25,165,824
static const size_t LOGITS_OFF = REFS_OFF + (size_t)(L_+1)*R_*3;   // 25,509,888

// ---------------- device state ----------------
__device__ float  g_query [R_*C_];
__device__ float  g_qpos  [R_*C_];
__device__ float  g_S     [R_*P_];
__device__ float  g_S2    [R_*P_];
__device__ float  g_logits[R_*P_];
__device__ float  g_lnpos [R_*C_];
__device__ float  g_ref   [R_*3];
__device__ float  g_b12i  [512];     // interleaved: 2c=g_b[c], 2c+1=be_b[c]
// half activations (GEMM A operands)
__device__ __half g_qsum_h  [R_*C_];
__device__ __half g_H_h     [R_*FF_];
__device__ __half g_q_h     [R_*C_];
__device__ __half g_probs_h [R_*P_];
__device__ __half g_coords_h[R_*P_*3];
// half weights (GEMM B operands, [K,N] row-major)
__device__ __half g_w1h  [L_*C_*FF_];
__device__ __half g_w2h  [L_*FF_*C_];
__device__ __half g_probh[L_*C_*P_];
__device__ __half g_posh [(P_*3)*C_];
__device__ __half g_w12h [P_*512];   // interleaved cols: 2c=g_w, 2c+1=be_w

// ---------------- reductions ----------------
__device__ __forceinline__ float warp_sum(float v){
#pragma unroll
    for (int o = 16; o; o >>= 1) v += __shfl_xor_sync(0xffffffffu, v, o);
    return v;
}
__device__ __forceinline__ float warp_max(float v){
#pragma unroll
    for (int o = 16; o; o >>= 1) v = fmaxf(v, __shfl_xor_sync(0xffffffffu, v, o));
    return v;
}

// ---------------- GEMM: 256 threads, BM=BN=128, BK=32, 3-stage cp.async ----------------
#define GA_LD 40
#define GB_LD 136
#define ST_A (128*GA_LD)
#define ST_B (32*GB_LD)
#define CT_LD 132
#define TG_SMEM_BYTES (128*CT_LD*4)   // 67584 > 3*(ST_A+ST_B)*2 = 56832

// lda = A row stride in elements (may exceed K for split-K slices)
__device__ __forceinline__ void gemm_load_stage(
    __half* Asm, __half* Bsm, int s, int k0, int tid, int bm, int bn,
    const __half* A, const __half* Bm, int lda, int N)
{
    __half* As = Asm + (size_t)s*ST_A;
    __half* Bs = Bsm + (size_t)s*ST_B;
#pragma unroll
    for (int i = 0; i < 2; i++) {
        int idx = tid + i * 256;                 // 0..511
        int ar = idx >> 2, ac = (idx & 3) * 8;   // A: 128 x 32 halfs
        __pipeline_memcpy_async(As + ar*GA_LD + ac,
            A + (size_t)(bm*128 + ar)*lda + k0 + ac, 16);
        int br = idx >> 4, bc = (idx & 15) * 8;  // B: 32 x 128 halfs
        __pipeline_memcpy_async(Bs + br*GB_LD + bc,
            Bm + (size_t)(k0 + br)*N + bn*128 + bc, 16);
    }
}

// leaves raw fp32 accum tile in Ct[128][CT_LD] (= smem base)
__device__ __forceinline__ void gemm_mainloop(
    char* smx, int tid, int bm, int bn,
    const __half* A, const __half* Bm, int K, int lda, int N)
{
    __half* Asm = (__half*)smx;
    __half* Bsm = Asm + 3*ST_A;
    const int wid = tid >> 5;
    const int warp_m = wid >> 2;     // 0..1 -> 64 rows
    const int warp_n = wid & 3;      // 0..3 -> 32 cols

    const int nIter = K / 32;
    gemm_load_stage(Asm, Bsm, 0, 0, tid, bm, bn, A, Bm, lda, N);
    __pipeline_commit();
    if (nIter > 1) gemm_load_stage(Asm, Bsm, 1, 32, tid, bm, bn, A, Bm, lda, N);
    __pipeline_commit();

    wmma::fragment<wmma::accumulator, 16, 16, 16, float> acc[4][2];
#pragma unroll
    for (int i = 0; i < 4; i++)
#pragma unroll
        for (int j = 0; j < 2; j++)
            wmma::fill_fragment(acc[i][j], 0.f);

    for (int it = 0; it < nIter; it++) {
        if (it + 2 < nIter)
            gemm_load_stage(Asm, Bsm, (it+2)%3, (it+2)*32, tid, bm, bn, A, Bm, lda, N);
        __pipeline_commit();
        __pipeline_wait_prior(2);
        __syncthreads();
        const __half* As = Asm + (size_t)(it % 3) * ST_A;
        const __half* Bs = Bsm + (size_t)(it % 3) * ST_B;
#pragma unroll
        for (int kk = 0; kk < 32; kk += 16) {
            wmma::fragment<wmma::matrix_a, 16, 16, 16, __half, wmma::row_major> af[4];
            wmma::fragment<wmma::matrix_b, 16, 16, 16, __half, wmma::row_major> bf[2];
#pragma unroll
            for (int i = 0; i < 4; i++)
                wmma::load_matrix_sync(af[i], As + (warp_m*64 + i*16)*GA_LD + kk, GA_LD);
#pragma unroll
            for (int j = 0; j < 2; j++)
                wmma::load_matrix_sync(bf[j], Bs + (size_t)kk*GB_LD + warp_n*32 + j*16, GB_LD);
#pragma unroll
            for (int i = 0; i < 4; i++)
#pragma unroll
                for (int j = 0; j < 2; j++)
                    wmma::mma_sync(acc[i][j], af[i], bf[j], acc[i][j]);
        }
        __syncthreads();
    }

    float* Ct = (float*)smx;
#pragma unroll
    for (int i = 0; i < 4; i++)
#pragma unroll
        for (int j = 0; j < 2; j++)
            wmma::store_matrix_sync(
                Ct + (size_t)(warp_m*64 + i*16)*CT_LD + warp_n*32 + j*16,
                acc[i][j], CT_LD, wmma::mem_row_major);
    __syncthreads();
}

// ---------------- GEMM: C = epi(A@B + bias [+Cres]) ----------------
// EPI: 0=relu(.+b), 1=Cres+.+b, 2=.+b
template<int EPI, bool OUTF, bool OUTH>
__global__ __launch_bounds__(256)
void hgemm(int M, int N, int K,
           const __half* __restrict__ A, const __half* __restrict__ Bm,
           const float* __restrict__ bias,
           const float* __restrict__ Cres, float* __restrict__ Cout,
           __half* __restrict__ CoutH)
{
    extern __shared__ __align__(16) char smx[];
    const int tid = threadIdx.x;
    const int bm = blockIdx.y, bn = blockIdx.x;
    gemm_mainloop(smx, tid, bm, bn, A, Bm, K, K, N);
    float* Ct = (float*)smx;

    const int row = tid >> 1;
    const int cb  = (tid & 1) * 64;
    int grow = bm * 128 + row;
    float* dst  = OUTF ? (Cout + (size_t)grow * N + bn * 128 + cb) : nullptr;
    __half* dsth = OUTH ? (CoutH + (size_t)grow * N + bn * 128 + cb) : nullptr;
    const float* bp = bias + bn * 128 + cb;
    const float* rp = (EPI == 1) ? (Cres + (size_t)grow * N + bn * 128 + cb) : nullptr;
#pragma unroll 4
    for (int c = 0; c < 64; c += 4) {
        float4 v = *(const float4*)&Ct[(size_t)row * CT_LD + cb + c];
        float4 b = *(const float4*)&bp[c];
        v.x += b.x; v.y += b.y; v.z += b.z; v.w += b.w;
        if (EPI == 0) {
            v.x = fmaxf(v.x, 0.f); v.y = fmaxf(v.y, 0.f);
            v.z = fmaxf(v.z, 0.f); v.w = fmaxf(v.w, 0.f);
        } else if (EPI == 1) {
            float4 cr = *(const float4*)&rp[c];
            v.x += cr.x; v.y += cr.y; v.z += cr.z; v.w += cr.w;
        }
        if (OUTF) *(float4*)&dst[c] = v;
        if (OUTH) {
            __half2 h0 = __floats2half2_rn(v.x, v.y);
            __half2 h1 = __floats2half2_rn(v.z, v.w);
            uint2 u; u.x = *(uint32_t*)&h0; u.y = *(uint32_t*)&h1;
            *(uint2*)&dsth[c] = u;
        }
    }
}

// ---------------- split-K S-GEMM: partial S over K half, raw store ----------------
// grid (2, R/128): blockIdx.x = k-split. Computes qh[:, ks*128:(ks+1)*128] @
// prob_w[ks*128:(ks+1)*128, :]. K=128 per block, lda=C_=256.
__global__ __launch_bounds__(256)
void sgemm_s(const __half* __restrict__ A,      // qh [R,256]
             const __half* __restrict__ Bm,     // prob_w half [256,128] (layer slice)
             float* __restrict__ S0, float* __restrict__ S1)
{
    extern __shared__ __align__(16) char smx[];
    const int tid = threadIdx.x;
    const int ks = blockIdx.x, bm = blockIdx.y;
    gemm_mainloop(smx, tid, bm, 0, A + ks*128, Bm + (size_t)ks*128*P_,
                  /*K=*/128, /*lda=*/C_, /*N=*/P_);
    float* Ct = (float*)smx;
    float* dst = (ks ? S1 : S0);

    const int row = tid >> 1;
    const int cb  = (tid & 1) * 64;
    int grow = bm * 128 + row;
#pragma unroll 4
    for (int c = 0; c < 64; c += 4) {
        float4 v = *(const float4*)&Ct[(size_t)row * CT_LD + cb + c];
        *(float4*)&dst[(size_t)grow * P_ + cb + c] = v;
    }
}

// ---------------- fused t12-GEMM + tail, coalesced epilogue ----------------
__global__ __launch_bounds__(256)
void sgemm_tail(const __half* __restrict__ A,         // probs_h [R,128]
                const __half* __restrict__ Bm,        // w12i [128,512]
                const float* __restrict__ b12i,
                const float* __restrict__ q,
                const float* __restrict__ lnp,
                const int* __restrict__ mask,
                float* __restrict__ qpos,
                __half* __restrict__ qsum_h)
{
    extern __shared__ __align__(16) char smx[];
    const int tid = threadIdx.x;
    const int bm = blockIdx.y, bn = blockIdx.x;
    gemm_mainloop(smx, tid, bm, bn, A, Bm, P_, P_, 512);
    float* Ct = (float*)smx;

    const int c_l = tid & 63;        // channel within block
    const int r0  = tid >> 6;        // 0..3
    const float t1b = b12i[bn*128 + 2*c_l];
    const float t2b = b12i[bn*128 + 2*c_l + 1];

#pragma unroll 4
    for (int rr = r0; rr < 128; rr += 4) {
        float t1 = Ct[(size_t)rr * CT_LD + 2*c_l]     + t1b;
        float t2 = Ct[(size_t)rr * CT_LD + 2*c_l + 1] + t2b;
        int grow = bm * 128 + rr;
        size_t idx = (size_t)grow * C_ + bn * 64 + c_l;
        float qpv = qpos[idx];
        if (mask[grow]) {
            qpv = lnp[idx] * t1 + t2;
            qpos[idx] = qpv;
        }
        qsum_h[idx] = __float2half_rn(q[idx] + qpv);
    }
}

// ---------------- one-shot setup ----------------
__global__ void setup_all(
    const float* __restrict__ layer_w1, const float* __restrict__ layer_w2,
    const float* __restrict__ prob_w,   const float* __restrict__ pos_w,
    const float* __restrict__ coords,
    const float* __restrict__ gw, const float* __restrict__ bew,
    const float* __restrict__ gb, const float* __restrict__ beb,
    const float* __restrict__ dprobs,
    const float* __restrict__ query, const float* __restrict__ query_pos,
    __half* __restrict__ w1h, __half* __restrict__ w2h,
    __half* __restrict__ prh, __half* __restrict__ psh,
    __half* __restrict__ coh, __half* __restrict__ w12h,
    float* __restrict__ b12i, float* __restrict__ lg,
    __half* __restrict__ qsum_h)
{
    int i = blockIdx.x * blockDim.x + threadIdx.x;
    if (i < R_*P_*3)     coh[i]  = __float2half_rn(coords[i]);
    if (i < L_*C_*FF_)   w1h[i]  = __float2half_rn(layer_w1[i]);
    if (i < L_*FF_*C_)   w2h[i]  = __float2half_rn(layer_w2[i]);
    if (i < L_*C_*P_)    prh[i]  = __float2half_rn(prob_w[i]);
    if (i < (P_*3)*C_)   psh[i]  = __float2half_rn(pos_w[i]);
    if (i < P_*512) {
        int row = i >> 9, col = i & 511;
        int c = col >> 1;
        float v = (col & 1) ? bew[row*256 + c] : gw[row*256 + c];
        w12h[i] = __float2half_rn(v);
    }
    if (i < 512)         b12i[i] = (i & 1) ? beb[i >> 1] : gb[i >> 1];
    if (i < R_*P_)       lg[i]   = logf(fmaxf(dprobs[i], 1e-8f));
    if (i < R_*C_)       qsum_h[i] = __float2half_rn(query[i] + query_pos[i]);
}

// ---------------- plain row LN (256 cols, 128 threads) ----------------
__global__ void ln_rows(const float* __restrict__ in, float* __restrict__ out)
{
    int row = blockIdx.x, t = threadIdx.x;
    int w = t >> 5, lane = t & 31;
    __shared__ float sr[8];
    float x0 = in[(size_t)row*C_ + t];
    float x1 = in[(size_t)row*C_ + 128 + t];
    float s1 = warp_sum(x0 + x1);
    float s2 = warp_sum(x0*x0 + x1*x1);
    if (lane == 0) { sr[w] = s1; sr[4+w] = s2; }
    __syncthreads();
    float m  = (sr[0]+sr[1]+sr[2]+sr[3]) * (1.f/256.f);
    float vv = (sr[4]+sr[5]+sr[6]+sr[7]) * (1.f/256.f) - m*m;
    float r  = rsqrtf(vv + 1e-5f);
    out[(size_t)row*C_ + t]       = (x0 - m) * r;
    out[(size_t)row*C_ + 128 + t] = (x1 - m) * r;
}

// ---------------- per-row fused: LN->interm, logits+softmax, ref einsum ----------------
__global__ void row_kernel(int layer,
                           const float* __restrict__ query,
                           const float* __restrict__ S0,
                           const float* __restrict__ S1,
                           const float* __restrict__ prob_b,
                           const __half* __restrict__ coords_h,
                           const int* __restrict__ mask,
                           const float* __restrict__ pn_scale,
                           const float* __restrict__ pn_bias,
                           float* __restrict__ logits_st,
                           __half* __restrict__ probs_h,
                           float* __restrict__ ref_st,
                           float* __restrict__ out)
{
    int row = blockIdx.x, t = threadIdx.x;
    int w = t >> 5, lane = t & 31;
    __shared__ float sr[12];

    float x0 = query[(size_t)row*C_ + t];
    float x1 = query[(size_t)row*C_ + 128 + t];
    float s1 = warp_sum(x0 + x1);
    float s2 = warp_sum(x0*x0 + x1*x1);
    if (lane == 0) { sr[w] = s1; sr[4+w] = s2; }
    __syncthreads();
    float m    = (sr[0]+sr[1]+sr[2]+sr[3]) * (1.f/256.f);
    float var  = (sr[4]+sr[5]+sr[6]+sr[7]) * (1.f/256.f) - m*m;
    float rstd = rsqrtf(var + 1e-5f);
    size_t ib = INTERM_OFF + (size_t)layer*R_*C_ + (size_t)row*C_;
    out[ib + t]       = (x0 - m)*rstd*pn_scale[t]       + pn_bias[t];
    out[ib + 128 + t] = (x1 - m)*rstd*pn_scale[128 + t] + pn_bias[128 + t];

    float mf = mask[row] ? 1.f : 0.f;
    size_t li = (size_t)row*P_ + t;
    float lg = logits_st[li] + (S0[li] + S1[li] + prob_b[t]) * mf;
    logits_st[li] = lg;
    out[LOGITS_OFF + (size_t)layer*R_*P_ + li] = lg;

    float mx = warp_max(lg);
    __syncthreads();
    if (lane == 0) sr[w] = mx;
    __syncthreads();
    mx = fmaxf(fmaxf(sr[0], sr[1]), fmaxf(sr[2], sr[3]));
    float e = __expf(lg - mx);
    float se = warp_sum(e);
    __syncthreads();
    if (lane == 0) sr[w] = se;
    __syncthreads();
    se = sr[0]+sr[1]+sr[2]+sr[3];
    float p = e / se;
    probs_h[li] = __float2half_rn(p);

    const __half* cr = coords_h + (size_t)row*P_*3 + (size_t)t*3;
    float r0 = warp_sum(p * __half2float(cr[0]));
    float r1 = warp_sum(p * __half2float(cr[1]));
    float r2 = warp_sum(p * __half2float(cr[2]));
    __syncthreads();
    if (lane == 0) { sr[w] = r0; sr[4+w] = r1; sr[8+w] = r2; }
    __syncthreads();
    if (t == 0) {
        float d0 = sr[0]+sr[1]+sr[2]+sr[3];
        float d1 = sr[4]+sr[5]+sr[6]+sr[7];
        float d2 = sr[8]+sr[9]+sr[10]+sr[11];
        float o0, o1, o2;
        if (mf > 0.f) { o0 = d0; o1 = d1; o2 = d2; }
        else { o0 = ref_st[row*3]; o1 = ref_st[row*3+1]; o2 = ref_st[row*3+2]; }
        ref_st[row*3] = o0; ref_st[row*3+1] = o1; ref_st[row*3+2] = o2;
        size_t rb = REFS_OFF + (size_t)(layer+1)*R_*3 + (size_t)row*3;
        out[rb] = o0; out[rb+1] = o1; out[rb+2] = o2;
    }
}

// ---------------- host ----------------
extern "C" void kernel_launch(void* const* d_in, const int* in_sizes, int n_in,
                              void* d_out, int out_size)
{
    const float*   query      = (const float*)d_in[0];
    const float*   query_pos  = (const float*)d_in[1];
    const float*   refpts     = (const float*)d_in[2];
    const float*   coords     = (const float*)d_in[3];
    const float*   dprobs     = (const float*)d_in[4];
    const int*     mask       = (const int*)d_in[5];
    const float*   layer_w1   = (const float*)d_in[6];
    const float*   layer_b1   = (const float*)d_in[7];
    const float*   layer_w2   = (const float*)d_in[8];
    const float*   layer_b2   = (const float*)d_in[9];
    const float*   prob_w     = (const float*)d_in[10];
    const float*   prob_b     = (const float*)d_in[11];
    const float*   pos_w      = (const float*)d_in[12];
    const float*   pos_b      = (const float*)d_in[13];
    const float*   g_wp       = (const float*)d_in[14];
    const float*   g_bp       = (const float*)d_in[15];
    const float*   be_w       = (const float*)d_in[16];
    const float*   be_b       = (const float*)d_in[17];
    const float*   pn_scale   = (const float*)d_in[18];
    const float*   pn_bias    = (const float*)d_in[19];
    float* out = (float*)d_out;

    float *q, *qp, *S0, *S1, *lg, *lnp, *ref, *b12i;
    __half *qsh, *Hh, *qh, *pbh, *coh, *w1h, *w2h, *prh, *psh, *w12h;
    cudaGetSymbolAddress((void**)&q,    g_query);
    cudaGetSymbolAddress((void**)&qp,   g_qpos);
    cudaGetSymbolAddress((void**)&S0,   g_S);
    cudaGetSymbolAddress((void**)&S1,   g_S2);
    cudaGetSymbolAddress((void**)&lg,   g_logits);
    cudaGetSymbolAddress((void**)&lnp,  g_lnpos);
    cudaGetSymbolAddress((void**)&ref,  g_ref);
    cudaGetSymbolAddress((void**)&b12i, g_b12i);
    cudaGetSymbolAddress((void**)&qsh,  g_qsum_h);
    cudaGetSymbolAddress((void**)&Hh,   g_H_h);
    cudaGetSymbolAddress((void**)&qh,   g_q_h);
    cudaGetSymbolAddress((void**)&pbh,  g_probs_h);
    cudaGetSymbolAddress((void**)&coh,  g_coords_h);
    cudaGetSymbolAddress((void**)&w1h,  g_w1h);
    cudaGetSymbolAddress((void**)&w2h,  g_w2h);
    cudaGetSymbolAddress((void**)&prh,  g_probh);
    cudaGetSymbolAddress((void**)&psh,  g_posh);
    cudaGetSymbolAddress((void**)&w12h, g_w12h);

    cudaFuncSetAttribute(hgemm<0,false,true>, cudaFuncAttributeMaxDynamicSharedMemorySize, TG_SMEM_BYTES);
    cudaFuncSetAttribute(hgemm<1,true,true>,  cudaFuncAttributeMaxDynamicSharedMemorySize, TG_SMEM_BYTES);
    cudaFuncSetAttribute(hgemm<2,true,false>, cudaFuncAttributeMaxDynamicSharedMemorySize, TG_SMEM_BYTES);
    cudaFuncSetAttribute(sgemm_s,    cudaFuncAttributeMaxDynamicSharedMemorySize, TG_SMEM_BYTES);
    cudaFuncSetAttribute(sgemm_tail, cudaFuncAttributeMaxDynamicSharedMemorySize, TG_SMEM_BYTES);

    // init fp32 state
    cudaMemcpyAsync(q,   query,  (size_t)R_*C_*4, cudaMemcpyDeviceToDevice);
    cudaMemcpyAsync(ref, refpts, (size_t)R_*3*4,  cudaMemcpyDeviceToDevice);
    cudaMemcpyAsync(qp,  query_pos, (size_t)R_*C_*4, cudaMemcpyDeviceToDevice);
    cudaMemcpyAsync(out + REFS_OFF, refpts, (size_t)R_*3*4, cudaMemcpyDeviceToDevice);

    // one-shot setup
    setup_all<<<(R_*P_*3 + 255)/256, 256>>>(
        layer_w1, layer_w2, prob_w, pos_w, coords,
        g_wp, be_w, g_bp, be_b, dprobs, query, query_pos,
        w1h, w2h, prh, psh, coh, w12h, b12i, lg, qsh);

    for (int i = 0; i < L_; i++) {
        // H = relu(qsum @ W1 + b1)  (half only)
        hgemm<0,false,true><<<dim3(FF_/128, R_/128), 256, TG_SMEM_BYTES>>>(R_, FF_, C_,
            qsh, w1h + (size_t)i*C_*FF_, layer_b1 + (size_t)i*FF_, nullptr, nullptr, Hh);
        // q = q + H @ W2 + b2  (fp32 + half)
        hgemm<1,true,true><<<dim3(C_/128, R_/128), 256, TG_SMEM_BYTES>>>(R_, C_, FF_,
            Hh, w2h + (size_t)i*FF_*C_, layer_b2 + (size_t)i*C_, q, q, qh);
        // split-K S-GEMM: S0 + S1 partials (bias applied in row_kernel)
        sgemm_s<<<dim3(2, R_/128), 256, TG_SMEM_BYTES>>>(
            qh, prh + (size_t)i*C_*P_, S0, S1);
        // per-row fused ops
        row_kernel<<<R_, 128>>>(i, q, S0, S1, prob_b + (size_t)i*P_, coh,
                                mask, pn_scale, pn_bias, lg, pbh, ref, out);
        if (i == 0) {
            // pos_base GEMM + LN deferred to first use
            hgemm<2,true,false><<<dim3(C_/128, R_/128), 256, TG_SMEM_BYTES>>>(R_, C_, P_*3,
                coh, psh, pos_b, nullptr, lnp, nullptr);
            ln_rows<<<R_, 128>>>(lnp, lnp);
        }
        // fused t12-GEMM + coalesced tail (skip on last layer)
        if (i + 1 < L_)
            sgemm_tail<<<dim3(4, R_/128), 256, TG_SMEM_BYTES>>>(
                pbh, w12h, b12i, q, lnp, mask, qp, qsh);
    }
    (void)in_sizes; (void)n_in; (void)out_size;
}

// round 17
// speedup vs baseline: 1.0611x; 1.0611x over previous
#include <cuda_runtime.h>
#include <cuda_pipeline.h>
#include <cuda_fp16.h>
#include <mma.h>
#include <cstdint>
#include <cstddef>

using namespace nvcuda;

#define L_  6
#define B_  8
#define Q_  2048
#define C_  256
#define P_  128
#define FF_ 1024
#define R_  (B_*Q_)   // 16384 rows

static const size_t INTERM_OFF = 0;
static const size_t REFS_OFF   = (size_t)L_*R_*C_;                 // 25,165,824
static const size_t LOGITS_OFF = REFS_OFF + (size_t)(L_+1)*R_*3;   // 25,509,888

// ---------------- device state ----------------
__device__ float  g_query [R_*C_];
__device__ float  g_qpos  [R_*C_];
__device__ float  g_S     [R_*P_];
__device__ float  g_logits[R_*P_];
__device__ float  g_lnpos [R_*C_];
__device__ float  g_t12   [R_*512];
__device__ float  g_ref   [R_*3];
__device__ float  g_b12   [512];
// half activations (GEMM A operands)
__device__ __half g_qsum_h  [R_*C_];
__device__ __half g_H_h     [R_*FF_];
__device__ __half g_q_h     [R_*C_];
__device__ __half g_probs_h [R_*P_];
__device__ __half g_coords_h[R_*P_*3];
// half weights (GEMM B operands, [K,N] row-major)
__device__ __half g_w1h  [L_*C_*FF_];
__device__ __half g_w2h  [L_*FF_*C_];
__device__ __half g_probh[L_*C_*P_];
__device__ __half g_posh [(P_*3)*C_];
__device__ __half g_w12h [P_*512];

// ---------------- reductions ----------------
__device__ __forceinline__ float warp_sum(float v){
#pragma unroll
    for (int o = 16; o; o >>= 1) v += __shfl_xor_sync(0xffffffffu, v, o);
    return v;
}
__device__ __forceinline__ float warp_max(float v){
#pragma unroll
    for (int o = 16; o; o >>= 1) v = fmaxf(v, __shfl_xor_sync(0xffffffffu, v, o));
    return v;
}

// ---------------- shared GEMM mainloop (round-10 config: 128 thr, 4 warps 2x2) ----------------
#define GA_LD 40     // As row stride in halfs
#define GB_LD 136    // Bs row stride in halfs
#define ST_A (128*GA_LD)
#define ST_B (32*GB_LD)
#define CT_LD 132
#define TG_SMEM_BYTES (128*CT_LD*4)   // 67584 > 3*(ST_A+ST_B)*2 = 56832

__device__ __forceinline__ void gemm_load_stage(
    __half* Asm, __half* Bsm, int s, int k0, int tid, int bm, int bn,
    const __half* A, const __half* Bm, int K, int N)
{
    __half* As = Asm + (size_t)s*ST_A;
    __half* Bs = Bsm + (size_t)s*ST_B;
#pragma unroll
    for (int i = 0; i < 4; i++) {
        int idx = tid + i * 128;
        int ar = idx >> 2, ac = (idx & 3) * 8;
        __pipeline_memcpy_async(As + ar*GA_LD + ac,
            A + (size_t)(bm*128 + ar)*K + k0 + ac, 16);
        int br = idx >> 4, bc = (idx & 15) * 8;
        __pipeline_memcpy_async(Bs + br*GB_LD + bc,
            Bm + (size_t)(k0 + br)*N + bn*128 + bc, 16);
    }
}

// leaves raw fp32 accum tile in Ct[128][CT_LD] (= smem base)
__device__ __forceinline__ void gemm_mainloop(
    char* smx, int tid, int bm, int bn,
    const __half* A, const __half* Bm, int K, int N)
{
    __half* Asm = (__half*)smx;
    __half* Bsm = Asm + 3*ST_A;
    const int wid = tid >> 5;
    const int warp_m = wid >> 1, warp_n = wid & 1;

    const int nIter = K / 32;
    gemm_load_stage(Asm, Bsm, 0, 0, tid, bm, bn, A, Bm, K, N);
    __pipeline_commit();
    if (nIter > 1) gemm_load_stage(Asm, Bsm, 1, 32, tid, bm, bn, A, Bm, K, N);
    __pipeline_commit();

    wmma::fragment<wmma::accumulator, 16, 16, 16, float> acc[4][4];
#pragma unroll
    for (int i = 0; i < 4; i++)
#pragma unroll
        for (int j = 0; j < 4; j++)
            wmma::fill_fragment(acc[i][j], 0.f);

    for (int it = 0; it < nIter; it++) {
        if (it + 2 < nIter)
            gemm_load_stage(Asm, Bsm, (it+2)%3, (it+2)*32, tid, bm, bn, A, Bm, K, N);
        __pipeline_commit();
        __pipeline_wait_prior(2);
        __syncthreads();
        const __half* As = Asm + (size_t)(it % 3) * ST_A;
        const __half* Bs = Bsm + (size_t)(it % 3) * ST_B;
#pragma unroll
        for (int kk = 0; kk < 32; kk += 16) {
            wmma::fragment<wmma::matrix_a, 16, 16, 16, __half, wmma::row_major> af[4];
            wmma::fragment<wmma::matrix_b, 16, 16, 16, __half, wmma::row_major> bf[4];
#pragma unroll
            for (int i = 0; i < 4; i++)
                wmma::load_matrix_sync(af[i], As + (warp_m*64 + i*16)*GA_LD + kk, GA_LD);
#pragma unroll
            for (int j = 0; j < 4; j++)
                wmma::load_matrix_sync(bf[j], Bs + (size_t)kk*GB_LD + warp_n*64 + j*16, GB_LD);
#pragma unroll
            for (int i = 0; i < 4; i++)
#pragma unroll
                for (int j = 0; j < 4; j++)
                    wmma::mma_sync(acc[i][j], af[i], bf[j], acc[i][j]);
        }
        __syncthreads();
    }

    float* Ct = (float*)smx;
#pragma unroll
    for (int i = 0; i < 4; i++)
#pragma unroll
        for (int j = 0; j < 4; j++)
            wmma::store_matrix_sync(
                Ct + (size_t)(warp_m*64 + i*16)*CT_LD + warp_n*64 + j*16,
                acc[i][j], CT_LD, wmma::mem_row_major);
    __syncthreads();
}

// ---------------- GEMM: C = epi(A@B + bias [+Cres]) ----------------
// EPI: 0=relu(.+b), 1=Cres+.+b, 2=.+b
template<int EPI, bool OUTF, bool OUTH>
__global__ __launch_bounds__(128)
void hgemm(int M, int N, int K,
           const __half* __restrict__ A, const __half* __restrict__ Bm,
           const float* __restrict__ bias,
           const float* __restrict__ Cres, float* __restrict__ Cout,
           __half* __restrict__ CoutH)
{
    extern __shared__ __align__(16) char smx[];
    const int tid = threadIdx.x;
    const int bm = blockIdx.y, bn = blockIdx.x;
    gemm_mainloop(smx, tid, bm, bn, A, Bm, K, N);
    float* Ct = (float*)smx;

    int grow = bm * 128 + tid;
    float* dst  = OUTF ? (Cout + (size_t)grow * N + bn * 128) : nullptr;
    __half* dsth = OUTH ? (CoutH + (size_t)grow * N + bn * 128) : nullptr;
    const float* bp = bias + bn * 128;
    const float* rp = (EPI == 1) ? (Cres + (size_t)grow * N + bn * 128) : nullptr;
#pragma unroll 4
    for (int c = 0; c < 128; c += 4) {
        float4 v = *(const float4*)&Ct[(size_t)tid * CT_LD + c];
        float4 b = *(const float4*)&bp[c];
        v.x += b.x; v.y += b.y; v.z += b.z; v.w += b.w;
        if (EPI == 0) {
            v.x = fmaxf(v.x, 0.f); v.y = fmaxf(v.y, 0.f);
            v.z = fmaxf(v.z, 0.f); v.w = fmaxf(v.w, 0.f);
        } else if (EPI == 1) {
            float4 cr = *(const float4*)&rp[c];
            v.x += cr.x; v.y += cr.y; v.z += cr.z; v.w += cr.w;
        }
        if (OUTF) *(float4*)&dst[c] = v;
        if (OUTH) {
            __half2 h0 = __floats2half2_rn(v.x, v.y);
            __half2 h1 = __floats2half2_rn(v.z, v.w);
            uint2 u; u.x = *(uint32_t*)&h0; u.y = *(uint32_t*)&h1;
            *(uint2*)&dsth[c] = u;
        }
    }
}

// ---------------- one-shot setup: all conversions + packs + inits ----------------
__global__ void setup_all(
    const float* __restrict__ layer_w1, const float* __restrict__ layer_w2,
    const float* __restrict__ prob_w,   const float* __restrict__ pos_w,
    const float* __restrict__ coords,
    const float* __restrict__ gw, const float* __restrict__ bew,
    const float* __restrict__ gb, const float* __restrict__ beb,
    const float* __restrict__ dprobs,
    const float* __restrict__ query, const float* __restrict__ query_pos,
    __half* __restrict__ w1h, __half* __restrict__ w2h,
    __half* __restrict__ prh, __half* __restrict__ psh,
    __half* __restrict__ coh, __half* __restrict__ w12h,
    float* __restrict__ b12, float* __restrict__ lg,
    __half* __restrict__ qsum_h)
{
    int i = blockIdx.x * blockDim.x + threadIdx.x;
    if (i < R_*P_*3)     coh[i]  = __float2half_rn(coords[i]);
    if (i < L_*C_*FF_)   w1h[i]  = __float2half_rn(layer_w1[i]);
    if (i < L_*FF_*C_)   w2h[i]  = __float2half_rn(layer_w2[i]);
    if (i < L_*C_*P_)    prh[i]  = __float2half_rn(prob_w[i]);
    if (i < (P_*3)*C_)   psh[i]  = __float2half_rn(pos_w[i]);
    if (i < P_*512) {
        int row = i >> 9, col = i & 511;
        float v = (col < 256) ? gw[row*256 + col] : bew[row*256 + col - 256];
        w12h[i] = __float2half_rn(v);
    }
    if (i < 512)         b12[i]  = (i < 256) ? gb[i] : beb[i - 256];
    if (i < R_*P_)       lg[i]   = logf(fmaxf(dprobs[i], 1e-8f));
    if (i < R_*C_)       qsum_h[i] = __float2half_rn(query[i] + query_pos[i]);
}

// ---------------- plain row LN (256 cols, 128 threads) ----------------
__global__ void ln_rows(const float* __restrict__ in, float* __restrict__ out)
{
    int row = blockIdx.x, t = threadIdx.x;
    int w = t >> 5, lane = t & 31;
    __shared__ float sr[8];
    float x0 = in[(size_t)row*C_ + t];
    float x1 = in[(size_t)row*C_ + 128 + t];
    float s1 = warp_sum(x0 + x1);
    float s2 = warp_sum(x0*x0 + x1*x1);
    if (lane == 0) { sr[w] = s1; sr[4+w] = s2; }
    __syncthreads();
    float m  = (sr[0]+sr[1]+sr[2]+sr[3]) * (1.f/256.f);
    float vv = (sr[4]+sr[5]+sr[6]+sr[7]) * (1.f/256.f) - m*m;
    float r  = rsqrtf(vv + 1e-5f);
    out[(size_t)row*C_ + t]       = (x0 - m) * r;
    out[(size_t)row*C_ + 128 + t] = (x1 - m) * r;
}

// ---------------- per-row fused: LN->interm, logits+softmax, ref einsum ----------------
__global__ void row_kernel(int layer,
                           const float* __restrict__ query,
                           const float* __restrict__ S,
                           const float* __restrict__ coords,
                           const int* __restrict__ mask,
                           const float* __restrict__ pn_scale,
                           const float* __restrict__ pn_bias,
                           float* __restrict__ logits_st,
                           __half* __restrict__ probs_h,
                           float* __restrict__ ref_st,
                           float* __restrict__ out)
{
    int row = blockIdx.x, t = threadIdx.x;
    int w = t >> 5, lane = t & 31;
    __shared__ float sr[12];

    float x0 = query[(size_t)row*C_ + t];
    float x1 = query[(size_t)row*C_ + 128 + t];
    float s1 = warp_sum(x0 + x1);
    float s2 = warp_sum(x0*x0 + x1*x1);
    if (lane == 0) { sr[w] = s1; sr[4+w] = s2; }
    __syncthreads();
    float m    = (sr[0]+sr[1]+sr[2]+sr[3]) * (1.f/256.f);
    float var  = (sr[4]+sr[5]+sr[6]+sr[7]) * (1.f/256.f) - m*m;
    float rstd = rsqrtf(var + 1e-5f);
    size_t ib = INTERM_OFF + (size_t)layer*R_*C_ + (size_t)row*C_;
    out[ib + t]       = (x0 - m)*rstd*pn_scale[t]       + pn_bias[t];
    out[ib + 128 + t] = (x1 - m)*rstd*pn_scale[128 + t] + pn_bias[128 + t];

    float mf = mask[row] ? 1.f : 0.f;
    size_t li = (size_t)row*P_ + t;
    float lg = logits_st[li] + S[li] * mf;
    logits_st[li] = lg;
    out[LOGITS_OFF + (size_t)layer*R_*P_ + li] = lg;

    float mx = warp_max(lg);
    __syncthreads();
    if (lane == 0) sr[w] = mx;
    __syncthreads();
    mx = fmaxf(fmaxf(sr[0], sr[1]), fmaxf(sr[2], sr[3]));
    float e = __expf(lg - mx);
    float se = warp_sum(e);
    __syncthreads();
    if (lane == 0) sr[w] = se;
    __syncthreads();
    se = sr[0]+sr[1]+sr[2]+sr[3];
    float p = e / se;
    probs_h[li] = __float2half_rn(p);

    const float* cr = coords + (size_t)row*P_*3 + (size_t)t*3;
    float r0 = warp_sum(p * cr[0]);
    float r1 = warp_sum(p * cr[1]);
    float r2 = warp_sum(p * cr[2]);
    __syncthreads();
    if (lane == 0) { sr[w] = r0; sr[4+w] = r1; sr[8+w] = r2; }
    __syncthreads();
    if (t == 0) {
        float d0 = sr[0]+sr[1]+sr[2]+sr[3];
        float d1 = sr[4]+sr[5]+sr[6]+sr[7];
        float d2 = sr[8]+sr[9]+sr[10]+sr[11];
        float o0, o1, o2;
        if (mf > 0.f) { o0 = d0; o1 = d1; o2 = d2; }
        else { o0 = ref_st[row*3]; o1 = ref_st[row*3+1]; o2 = ref_st[row*3+2]; }
        ref_st[row*3] = o0; ref_st[row*3+1] = o1; ref_st[row*3+2] = o2;
        size_t rb = REFS_OFF + (size_t)(layer+1)*R_*3 + (size_t)row*3;
        out[rb] = o0; out[rb+1] = o1; out[rb+2] = o2;
    }
}

// ---------------- layer tail: masked qpos update + qsum_h (coalesced) ----------------
__global__ void layer_tail(const float* __restrict__ q,
                           const float* __restrict__ t12,
                           const float* __restrict__ lnp, const int* __restrict__ mask,
                           float* __restrict__ qpos, __half* __restrict__ qsum_h)
{
    int idx = blockIdx.x * blockDim.x + threadIdx.x;
    if (idx >= R_*C_) return;
    int row = idx >> 8, c = idx & 255;
    float qp = qpos[idx];
    if (mask[row]) {
        float t1 = t12[(size_t)row*512 + c];
        float t2 = t12[(size_t)row*512 + 256 + c];
        qp = lnp[idx] * t1 + t2;
        qpos[idx] = qp;
    }
    qsum_h[idx] = __float2half_rn(q[idx] + qp);
}

// ---------------- host ----------------
extern "C" void kernel_launch(void* const* d_in, const int* in_sizes, int n_in,
                              void* d_out, int out_size)
{
    const float*   query      = (const float*)d_in[0];
    const float*   query_pos  = (const float*)d_in[1];
    const float*   refpts     = (const float*)d_in[2];
    const float*   coords     = (const float*)d_in[3];
    const float*   dprobs     = (const float*)d_in[4];
    const int*     mask       = (const int*)d_in[5];
    const float*   layer_w1   = (const float*)d_in[6];
    const float*   layer_b1   = (const float*)d_in[7];
    const float*   layer_w2   = (const float*)d_in[8];
    const float*   layer_b2   = (const float*)d_in[9];
    const float*   prob_w     = (const float*)d_in[10];
    const float*   prob_b     = (const float*)d_in[11];
    const float*   pos_w      = (const float*)d_in[12];
    const float*   pos_b      = (const float*)d_in[13];
    const float*   g_wp       = (const float*)d_in[14];
    const float*   g_bp       = (const float*)d_in[15];
    const float*   be_w       = (const float*)d_in[16];
    const float*   be_b       = (const float*)d_in[17];
    const float*   pn_scale   = (const float*)d_in[18];
    const float*   pn_bias    = (const float*)d_in[19];
    float* out = (float*)d_out;

    float *q, *qp, *S, *lg, *lnp, *t12, *ref, *b12;
    __half *qsh, *Hh, *qh, *pbh, *coh, *w1h, *w2h, *prh, *psh, *w12h;
    cudaGetSymbolAddress((void**)&q,    g_query);
    cudaGetSymbolAddress((void**)&qp,   g_qpos);
    cudaGetSymbolAddress((void**)&S,    g_S);
    cudaGetSymbolAddress((void**)&lg,   g_logits);
    cudaGetSymbolAddress((void**)&lnp,  g_lnpos);
    cudaGetSymbolAddress((void**)&t12,  g_t12);
    cudaGetSymbolAddress((void**)&ref,  g_ref);
    cudaGetSymbolAddress((void**)&b12,  g_b12);
    cudaGetSymbolAddress((void**)&qsh,  g_qsum_h);
    cudaGetSymbolAddress((void**)&Hh,   g_H_h);
    cudaGetSymbolAddress((void**)&qh,   g_q_h);
    cudaGetSymbolAddress((void**)&pbh,  g_probs_h);
    cudaGetSymbolAddress((void**)&coh,  g_coords_h);
    cudaGetSymbolAddress((void**)&w1h,  g_w1h);
    cudaGetSymbolAddress((void**)&w2h,  g_w2h);
    cudaGetSymbolAddress((void**)&prh,  g_probh);
    cudaGetSymbolAddress((void**)&psh,  g_posh);
    cudaGetSymbolAddress((void**)&w12h, g_w12h);

    cudaFuncSetAttribute(hgemm<0,false,true>, cudaFuncAttributeMaxDynamicSharedMemorySize, TG_SMEM_BYTES);
    cudaFuncSetAttribute(hgemm<1,true,true>,  cudaFuncAttributeMaxDynamicSharedMemorySize, TG_SMEM_BYTES);
    cudaFuncSetAttribute(hgemm<2,true,false>, cudaFuncAttributeMaxDynamicSharedMemorySize, TG_SMEM_BYTES);

    // init fp32 state
    cudaMemcpyAsync(q,   query,  (size_t)R_*C_*4, cudaMemcpyDeviceToDevice);
    cudaMemcpyAsync(ref, refpts, (size_t)R_*3*4,  cudaMemcpyDeviceToDevice);
    cudaMemcpyAsync(qp,  query_pos, (size_t)R_*C_*4, cudaMemcpyDeviceToDevice);
    cudaMemcpyAsync(out + REFS_OFF, refpts, (size_t)R_*3*4, cudaMemcpyDeviceToDevice);

    // one-shot setup (replaces 5x cvt_h + pack_gb + init_kernel; same math)
    setup_all<<<(R_*P_*3 + 255)/256, 256>>>(
        layer_w1, layer_w2, prob_w, pos_w, coords,
        g_wp, be_w, g_bp, be_b, dprobs, query, query_pos,
        w1h, w2h, prh, psh, coh, w12h, b12, lg, qsh);

    // pos_base = coords @ pos_w + pos_b -> lnp; then LN in-place (per-row safe)
    hgemm<2,true,false><<<dim3(C_/128, R_/128), 128, TG_SMEM_BYTES>>>(R_, C_, P_*3,
        coh, psh, pos_b, nullptr, lnp, nullptr);
    ln_rows<<<R_, 128>>>(lnp, lnp);

    for (int i = 0; i < L_; i++) {
        // H = relu(qsum @ W1 + b1)  (half only — fp32 H is dead)
        hgemm<0,false,true><<<dim3(FF_/128, R_/128), 128, TG_SMEM_BYTES>>>(R_, FF_, C_,
            qsh, w1h + (size_t)i*C_*FF_, layer_b1 + (size_t)i*FF_, nullptr, nullptr, Hh);
        // q = q + H @ W2 + b2  (fp32 + half)
        hgemm<1,true,true><<<dim3(C_/128, R_/128), 128, TG_SMEM_BYTES>>>(R_, C_, FF_,
            Hh, w2h + (size_t)i*FF_*C_, layer_b2 + (size_t)i*C_, q, q, qh);
        // S = q @ prob_w + prob_b (fp32 out)
        hgemm<2,true,false><<<dim3(P_/128, R_/128), 128, TG_SMEM_BYTES>>>(R_, P_, C_,
            qh, prh + (size_t)i*C_*P_, prob_b + (size_t)i*P_, nullptr, S, nullptr);
        // per-row fused ops (16384-block parallel)
        row_kernel<<<R_, 128>>>(i, q, S, coords, mask, pn_scale, pn_bias,
                                lg, pbh, ref, out);
        // [t1|t2] GEMM + coalesced tail (skip on last layer — feeds next layer only)
        if (i + 1 < L_) {
            hgemm<2,true,false><<<dim3(512/128, R_/128), 128, TG_SMEM_BYTES>>>(R_, 512, P_,
                pbh, w12h, b12, nullptr, t12, nullptr);
            layer_tail<<<(R_*C_ + 255)/256, 256>>>(q, t12, lnp, mask, qp, qsh);
        }
    }
    (void)in_sizes; (void)n_in; (void)out_size;
}